// round 16
// baseline (speedup 1.0000x reference)
#include <cuda_runtime.h>
#include <cuda_bf16.h>
#include <mma.h>
#include <math.h>
#include <stdint.h>

using namespace nvcuda;

// ---------------- problem constants ----------------
#define BB     2
#define CC     960
#define HH     20
#define WW     40
#define HWP    800        // H*W
#define AA     12
#define NANCH  9600       // HWP*AA
#define PRE    1000
#define POST   500
#define POOLN  7
#define FDIM   47040      // CC*49
#define FC     1024
#define BBOX_CLIP 4.135166556742356f
#define NMS_TH 0.7f

#define MPAD   1024       // padded M for fc6 GEMM

// ---------------- scratch (static device globals; no allocations) ----------------
__device__ float              g_wT[9 * CC * CC];    // conv weights transposed [tap][ci][co]
__device__ float              g_t[BB * CC * HWP];   // conv output (relu)
__device__ float              g_obj[BB * NANCH];
__device__ float              g_dlt[BB * NANCH * 4];
__device__ unsigned long long g_keys[BB * NANCH];
__device__ int                g_topidx[BB * PRE];
__device__ float              g_boxes[BB * PRE * 4];
__device__ int                g_keep[BB * POST];
__device__ float              g_x6[BB * POST * FC];
__device__ float              g_x7[BB * POST * FC];

// fc6 bf16 split buffers. g_a6_* rows 1000..1023 are never written -> stay zero (BSS).
__device__ __align__(128) __nv_bfloat16 g_a6_hi[MPAD * FDIM];    // fc6 A = pooled [M x K]
__device__ __align__(128) __nv_bfloat16 g_a6_lo[MPAD * FDIM];
__device__ __align__(128) __nv_bfloat16 g_b6_hi[FDIM * FC];      // fc6 B = fc6_w  [K x N]
__device__ __align__(128) __nv_bfloat16 g_b6_lo[FDIM * FC];

// ---------------- split helper ----------------
__device__ __forceinline__ void split_bf16(float v, __nv_bfloat16& hi, __nv_bfloat16& lo) {
    hi = __float2bfloat16(v);
    lo = __float2bfloat16(v - __bfloat162float(hi));
}

// ---------------- 1. weight transpose ----------------
__global__ void __launch_bounds__(256) k_transpose_w(const float* __restrict__ w) {
    int d = blockIdx.x * blockDim.x + threadIdx.x;
    if (d >= 9 * CC * CC) return;
    int tap = d / (CC * CC);
    int rem = d - tap * (CC * CC);
    int ci = rem / CC;
    int co = rem - ci * CC;
    int ky = tap / 3, kx = tap - ky * 3;
    g_wT[d] = w[((co * CC + ci) * 3 + ky) * 3 + kx];
}

// ---------------- 2. 3x3 conv + bias + relu (128x128 tile, 8x8/thread fp32) -----
// Shifted-GEMM: t[co][p] = relu(sum_{tap,ci} Wt[tap][ci][co] * x[ci][p shifted] + bias)
__global__ void __launch_bounds__(256) k_conv2(const float* __restrict__ x,
                                               const float* __restrict__ bias) {
    __shared__ float Ws[8][128];   // [k][co]
    __shared__ float Xs[8][128];   // [k][p]
    const int b  = blockIdx.z;
    const int m0 = blockIdx.y * 128;   // co base
    const int p0 = blockIdx.x * 128;   // spatial base
    const int tid = threadIdx.x;
    const int ty = tid >> 4, tx = tid & 15;

    float acc[8][8];
#pragma unroll
    for (int i = 0; i < 8; i++)
#pragma unroll
        for (int j = 0; j < 8; j++) acc[i][j] = 0.f;

    for (int tap = 0; tap < 9; ++tap) {
        const int dy = tap / 3 - 1, dx = tap % 3 - 1;
        for (int ci0 = 0; ci0 < CC; ci0 += 8) {
            // stage Ws: 8 k-rows x 128 co (guard co fringe at m0=896)
#pragma unroll
            for (int i = 0; i < 4; i++) {
                int e = tid + i * 256;
                int k = e >> 7, m = e & 127;
                int co = m0 + m;
                Ws[k][m] = (co < CC) ? g_wT[(tap * CC + ci0 + k) * CC + co] : 0.f;
            }
            // stage Xs: 8 k-rows x 128 p (shifted, zero at borders)
#pragma unroll
            for (int i = 0; i < 4; i++) {
                int e = tid + i * 256;
                int k = e >> 7, j = e & 127;
                int p = p0 + j;
                float v = 0.f;
                if (p < HWP) {
                    int y = p / WW, xx = p - y * WW;
                    int yy = y + dy, xs = xx + dx;
                    if (yy >= 0 && yy < HH && xs >= 0 && xs < WW)
                        v = x[((b * CC + ci0 + k) * HH + yy) * WW + xs];
                }
                Xs[k][j] = v;
            }
            __syncthreads();
#pragma unroll
            for (int k = 0; k < 8; k++) {
                float a[8], bb[8];
#pragma unroll
                for (int i = 0; i < 4; i++) {
                    a[i]     = Ws[k][ty * 4 + i];
                    a[i + 4] = Ws[k][64 + ty * 4 + i];
                    bb[i]     = Xs[k][tx * 4 + i];
                    bb[i + 4] = Xs[k][64 + tx * 4 + i];
                }
#pragma unroll
                for (int i = 0; i < 8; i++)
#pragma unroll
                    for (int j = 0; j < 8; j++)
                        acc[i][j] += a[i] * bb[j];
            }
            __syncthreads();
        }
    }
#pragma unroll
    for (int i = 0; i < 8; i++) {
        int co = m0 + ((i < 4) ? (ty * 4 + i) : (64 + ty * 4 + i - 4));
        if (co < CC) {
            float bs = bias[co];
#pragma unroll
            for (int j = 0; j < 8; j++) {
                int p = p0 + ((j < 4) ? (tx * 4 + j) : (64 + tx * 4 + j - 4));
                if (p < HWP) {
                    float v = acc[i][j] + bs;
                    g_t[((size_t)b * CC + co) * HWP + p] = v > 0.f ? v : 0.f;
                }
            }
        }
    }
}

// ---------------- fc6 weight split ----------------
__global__ void __launch_bounds__(256) k_split_fc6w(const float* __restrict__ w) {
    int i = blockIdx.x * 256 + threadIdx.x;
    if (i >= FDIM * FC) return;
    __nv_bfloat16 hi, lo; split_bf16(w[i], hi, lo);
    g_b6_hi[i] = hi; g_b6_lo[i] = lo;
}

// ---------------- fc6: bf16-split wmma GEMM (128x128 tile, K32 steps) -----------
#define LDA 40    // 32 + 8 bf16: 80B row stride
#define LDB 136   // 128 + 8 bf16: 272B row stride
#define LDS 16    // epilogue scratch ld: 64B (wmma-legal)

__global__ void __launch_bounds__(256) k_fc6_wmma(const float* __restrict__ bias) {
    __shared__ __align__(16) __nv_bfloat16 AsH[128 * LDA], AsL[128 * LDA];
    __shared__ __align__(16) __nv_bfloat16 BsH[32 * LDB],  BsL[32 * LDB];
    __shared__ __align__(16) float scr[8][16 * LDS];

    const int tid = threadIdx.x, wid = tid >> 5, lane = tid & 31;
    const int m0 = blockIdx.y * 128, n0 = blockIdx.x * 128;
    const int wm = wid >> 1, wn = wid & 1;

    wmma::fragment<wmma::accumulator, 16, 16, 16, float> acc[2][4];
#pragma unroll
    for (int i = 0; i < 2; i++)
#pragma unroll
        for (int j = 0; j < 4; j++) wmma::fill_fragment(acc[i][j], 0.f);

    for (int k0 = 0; k0 < FDIM; k0 += 32) {
#pragma unroll
        for (int e = tid; e < 512; e += 256) {
            int r = e >> 2, q = e & 3;
            size_t go = (size_t)(m0 + r) * FDIM + k0 + q * 8;
            *(uint4*)&AsH[r * LDA + q * 8] = *(const uint4*)&g_a6_hi[go];
            *(uint4*)&AsL[r * LDA + q * 8] = *(const uint4*)&g_a6_lo[go];
        }
#pragma unroll
        for (int e = tid; e < 512; e += 256) {
            int r = e >> 4, q = e & 15;
            size_t go = (size_t)(k0 + r) * FC + n0 + q * 8;
            *(uint4*)&BsH[r * LDB + q * 8] = *(const uint4*)&g_b6_hi[go];
            *(uint4*)&BsL[r * LDB + q * 8] = *(const uint4*)&g_b6_lo[go];
        }
        __syncthreads();

#pragma unroll
        for (int kk = 0; kk < 2; kk++) {
            wmma::fragment<wmma::matrix_a, 16, 16, 16, __nv_bfloat16, wmma::row_major> ah[2], al[2];
            wmma::fragment<wmma::matrix_b, 16, 16, 16, __nv_bfloat16, wmma::row_major> bh[4], bl[4];
#pragma unroll
            for (int i = 0; i < 2; i++) {
                wmma::load_matrix_sync(ah[i], &AsH[(wm * 32 + i * 16) * LDA + kk * 16], LDA);
                wmma::load_matrix_sync(al[i], &AsL[(wm * 32 + i * 16) * LDA + kk * 16], LDA);
            }
#pragma unroll
            for (int j = 0; j < 4; j++) {
                wmma::load_matrix_sync(bh[j], &BsH[(kk * 16) * LDB + wn * 64 + j * 16], LDB);
                wmma::load_matrix_sync(bl[j], &BsL[(kk * 16) * LDB + wn * 64 + j * 16], LDB);
            }
#pragma unroll
            for (int i = 0; i < 2; i++)
#pragma unroll
                for (int j = 0; j < 4; j++) {
                    wmma::mma_sync(acc[i][j], ah[i], bh[j], acc[i][j]);
                    wmma::mma_sync(acc[i][j], ah[i], bl[j], acc[i][j]);
                    wmma::mma_sync(acc[i][j], al[i], bh[j], acc[i][j]);
                }
        }
        __syncthreads();
    }

#pragma unroll
    for (int i = 0; i < 2; i++)
#pragma unroll
        for (int j = 0; j < 4; j++) {
            wmma::store_matrix_sync(&scr[wid][0], acc[i][j], LDS, wmma::mem_row_major);
            __syncwarp();
#pragma unroll
            for (int e = lane; e < 256; e += 32) {
                int r = e >> 4, c = e & 15;
                int gm = m0 + wm * 32 + i * 16 + r;
                int gn = n0 + wn * 64 + j * 16 + c;
                if (gm < BB * POST) {
                    float v = scr[wid][r * LDS + c] + bias[gn];
                    g_x6[(size_t)gm * FC + gn] = v > 0.f ? v : 0.f;
                }
            }
            __syncwarp();
        }
}

// ---------------- rpn cls/reg heads ----------------
__global__ void __launch_bounds__(128) k_rpn(const float* __restrict__ cls_w,
                                             const float* __restrict__ cls_b,
                                             const float* __restrict__ reg_w,
                                             const float* __restrict__ reg_b) {
    const int p = blockIdx.x * blockDim.x + threadIdx.x;
    if (p >= HWP) return;
    const int r = blockIdx.y;   // 0..59
    const int b = blockIdx.z;
    const float* wrow = (r < AA) ? (cls_w + r * CC) : (reg_w + (r - AA) * CC);
    float acc = (r < AA) ? cls_b[r] : reg_b[r - AA];
    const float* tp = g_t + (size_t)b * CC * HWP + p;
    for (int k = 0; k < CC; k++)
        acc += tp[k * HWP] * __ldg(&wrow[k]);
    if (r < AA) {
        g_obj[b * NANCH + p * AA + r] = acc;
    } else {
        int a48 = r - AA;
        int a = a48 >> 2, c = a48 & 3;
        g_dlt[((size_t)b * NANCH + p * AA + a) * 4 + c] = acc;
    }
}

// ---------------- top-1000 via exact rank selection ----------------
__device__ __forceinline__ unsigned int mapf(float f) {
    unsigned int u = __float_as_uint(f);
    return (u & 0x80000000u) ? ~u : (u | 0x80000000u);
}
__global__ void __launch_bounds__(256) k_key() {
    int i = blockIdx.x * blockDim.x + threadIdx.x;
    if (i >= BB * NANCH) return;
    int b = i / NANCH;
    int j = i - b * NANCH;
    unsigned int u = mapf(g_obj[i]);
    g_keys[i] = ((unsigned long long)(~u) << 32) | (unsigned int)j;
}
__global__ void __launch_bounds__(256) k_rank() {
    const int b = blockIdx.y;
    const int i = blockIdx.x * blockDim.x + threadIdx.x;
    if (i >= NANCH) return;
    const unsigned long long* keys = g_keys + (size_t)b * NANCH;
    const unsigned long long ki = keys[i];
    int cnt = 0;
    for (int j = 0; j < NANCH; j++)
        cnt += (keys[j] < ki);
    if (cnt < PRE)
        g_topidx[b * PRE + cnt] = i;
}

// ---------------- decode + clip ----------------
__global__ void __launch_bounds__(256) k_decode() {
    const int b = blockIdx.y;
    const int i = blockIdx.x * blockDim.x + threadIdx.x;
    if (i >= PRE) return;
    int idx = g_topidx[b * PRE + i];
    int p = idx / AA, a = idx - p * AA;
    int y = p / WW, xx = p - y * WW;
    int r = a >> 2, s = a & 3;
    const float sizes[4] = {32.f, 64.f, 128.f, 256.f};
    const float ratios[3] = {0.5f, 1.f, 2.f};
    float hr = sqrtf(ratios[r]);
    float wr = 1.0f / hr;
    float wa = wr * sizes[s];
    float ha = hr * sizes[s];
    float cxa = xx * 16.0f, cya = y * 16.0f;
    const float* d = &g_dlt[((size_t)b * NANCH + idx) * 4];
    float dx = d[0], dy = d[1];
    float dw = fminf(d[2], BBOX_CLIP), dh = fminf(d[3], BBOX_CLIP);
    float cx = dx * wa + cxa, cy = dy * ha + cya;
    float w = expf(dw) * wa, h = expf(dh) * ha;
    float x1 = cx - 0.5f * w, y1 = cy - 0.5f * h;
    float x2 = cx + 0.5f * w, y2 = cy + 0.5f * h;
    x1 = fminf(fmaxf(x1, 0.f), 640.f);
    y1 = fminf(fmaxf(y1, 0.f), 320.f);
    x2 = fminf(fmaxf(x2, 0.f), 640.f);
    y2 = fminf(fmaxf(y2, 0.f), 320.f);
    float* bx = &g_boxes[((size_t)b * PRE + i) * 4];
    bx[0] = x1; bx[1] = y1; bx[2] = x2; bx[3] = y2;
}

// ---------------- NMS ----------------
__global__ void __launch_bounds__(1024) k_nms() {
    __shared__ float bx1[PRE], by1[PRE], bx2[PRE], by2[PRE], barea[PRE];
    __shared__ int msk[PRE];
    const int b = blockIdx.x, j = threadIdx.x;
    if (j < PRE) {
        const float* bx = &g_boxes[((size_t)b * PRE + j) * 4];
        bx1[j] = bx[0]; by1[j] = bx[1]; bx2[j] = bx[2]; by2[j] = bx[3];
        barea[j] = (bx[2] - bx[0]) * (bx[3] - bx[1]);
        msk[j] = 1;
    }
    __syncthreads();
    for (int i = 0; i < PRE - 1; i++) {
        bool mi = (msk[i] != 0);
        if (mi && j < PRE && j > i && msk[j]) {
            float lx = fmaxf(bx1[i], bx1[j]);
            float ly = fmaxf(by1[i], by1[j]);
            float rx = fminf(bx2[i], bx2[j]);
            float ry = fminf(by2[i], by2[j]);
            float w = fmaxf(rx - lx, 0.f), h = fmaxf(ry - ly, 0.f);
            float inter = w * h;
            float iou = inter / (barea[i] + barea[j] - inter + 1e-6f);
            if (iou > NMS_TH) msk[j] = 0;
        }
        __syncthreads();
    }
    if (j == 0) {
        int k = 0;
        for (int i = 0; i < PRE && k < POST; i++)
            if (msk[i]) g_keep[b * POST + k++] = i;
        for (int i = 0; i < PRE && k < POST; i++)
            if (!msk[i]) g_keep[b * POST + k++] = i;
    }
}

// ---------------- ROI align (warp-per-channel, coalesced, fused bf16 split) -----
struct Geo { int i00, i01, i10, i11; float w00, w01, w10, w11; };
__global__ void __launch_bounds__(256) k_roi(const float* __restrict__ feat) {
    __shared__ float rows[8][HWP];
    __shared__ Geo geo[49 * 4];
    __shared__ float box[4];
    const int ng = blockIdx.x;
    const int b = ng / POST;
    const int nl = ng - b * POST;
    const int tid = threadIdx.x;
    const int wid = tid >> 5, lane = tid & 31;

    if (tid == 0) {
        int kidx = g_keep[b * POST + nl];
        const float* bx = &g_boxes[((size_t)b * PRE + kidx) * 4];
        box[0] = bx[0]; box[1] = bx[1]; box[2] = bx[2]; box[3] = bx[3];
    }
    __syncthreads();
    if (tid < 49 * 4) {
        int bin = tid >> 2, s = tid & 3;
        int py = bin / POOLN, px = bin - py * POOLN;
        int sy = s >> 1, sx = s & 1;
        float x1 = box[0] / 16.0f, y1 = box[1] / 16.0f;
        float x2 = box[2] / 16.0f, y2 = box[3] / 16.0f;
        float rw = fmaxf(x2 - x1, 1.0f), rh = fmaxf(y2 - y1, 1.0f);
        float bw = rw / POOLN, bh = rh / POOLN;
        float suby = (sy == 0) ? 0.25f : 0.75f;
        float subx = (sx == 0) ? 0.25f : 0.75f;
        float ys = y1 + (py + suby) * bh;
        float xs = x1 + (px + subx) * bw;
        ys = fminf(fmaxf(ys, 0.f), (float)(HH - 1));
        xs = fminf(fmaxf(xs, 0.f), (float)(WW - 1));
        int y0 = (int)floorf(ys), x0 = (int)floorf(xs);
        int y1i = min(y0 + 1, HH - 1), x1i = min(x0 + 1, WW - 1);
        float wy = ys - (float)y0, wx = xs - (float)x0;
        Geo g;
        g.i00 = y0 * WW + x0;  g.i01 = y0 * WW + x1i;
        g.i10 = y1i * WW + x0; g.i11 = y1i * WW + x1i;
        g.w00 = (1.f - wy) * (1.f - wx) * 0.25f;
        g.w01 = (1.f - wy) * wx * 0.25f;
        g.w10 = wy * (1.f - wx) * 0.25f;
        g.w11 = wy * wx * 0.25f;
        geo[tid] = g;
    }
    __syncthreads();

    for (int c = wid; c < CC; c += 8) {
        const float* f = feat + ((size_t)b * CC + c) * HWP;
#pragma unroll
        for (int i = lane; i < HWP; i += 32)
            rows[wid][i] = f[i];
        __syncwarp();
        size_t dbase = (size_t)ng * FDIM + (size_t)c * 49;
        for (int bin = lane; bin < 49; bin += 32) {
            float acc = 0.f;
#pragma unroll
            for (int s = 0; s < 4; s++) {
                Geo g = geo[bin * 4 + s];
                acc += g.w00 * rows[wid][g.i00] + g.w01 * rows[wid][g.i01] +
                       g.w10 * rows[wid][g.i10] + g.w11 * rows[wid][g.i11];
            }
            __nv_bfloat16 hi, lo; split_bf16(acc, hi, lo);
            g_a6_hi[dbase + bin] = hi;
            g_a6_lo[dbase + bin] = lo;
        }
        __syncwarp();
    }
}

// ---------------- fp32 tiled GEMM (fc7) ----------------
__global__ void __launch_bounds__(256) k_gemm(const float* __restrict__ A,
                                              const float* __restrict__ Bm,
                                              const float* __restrict__ bias,
                                              float* __restrict__ Cc,
                                              int M, int N, int K, int dorelu) {
    __shared__ float As[16][64];
    __shared__ float Bs[16][64];
    const int n0 = blockIdx.x * 64;
    const int m0 = blockIdx.y * 64;
    const int tid = threadIdx.x;
    const int ti = tid >> 4, tj = tid & 15;
    float acc[4][4];
#pragma unroll
    for (int i = 0; i < 4; i++)
#pragma unroll
        for (int j = 0; j < 4; j++) acc[i][j] = 0.f;

    for (int k0 = 0; k0 < K; k0 += 16) {
#pragma unroll
        for (int i = 0; i < 4; i++) {
            int e = tid + i * 256;
            int m = e >> 4, k = e & 15;
            int row = m0 + m;
            As[k][m] = (row < M) ? A[(size_t)row * K + k0 + k] : 0.f;
        }
#pragma unroll
        for (int i = 0; i < 4; i++) {
            int e = tid + i * 256;
            int k = e >> 6, n = e & 63;
            Bs[k][n] = Bm[(size_t)(k0 + k) * N + n0 + n];
        }
        __syncthreads();
#pragma unroll
        for (int k = 0; k < 16; k++) {
            float4 av = *(const float4*)&As[k][ti * 4];
            float4 bv = *(const float4*)&Bs[k][tj * 4];
            acc[0][0] += av.x * bv.x; acc[0][1] += av.x * bv.y; acc[0][2] += av.x * bv.z; acc[0][3] += av.x * bv.w;
            acc[1][0] += av.y * bv.x; acc[1][1] += av.y * bv.y; acc[1][2] += av.y * bv.z; acc[1][3] += av.y * bv.w;
            acc[2][0] += av.z * bv.x; acc[2][1] += av.z * bv.y; acc[2][2] += av.z * bv.z; acc[2][3] += av.z * bv.w;
            acc[3][0] += av.w * bv.x; acc[3][1] += av.w * bv.y; acc[3][2] += av.w * bv.z; acc[3][3] += av.w * bv.w;
        }
        __syncthreads();
    }
#pragma unroll
    for (int ii = 0; ii < 4; ii++) {
        int row = m0 + ti * 4 + ii;
        if (row < M) {
#pragma unroll
            for (int jj = 0; jj < 4; jj++) {
                int col = n0 + tj * 4 + jj;
                float v = acc[ii][jj] + bias[col];
                if (dorelu) v = v > 0.f ? v : 0.f;
                Cc[(size_t)row * N + col] = v;
            }
        }
    }
}

// ---------------- final heads ----------------
__global__ void __launch_bounds__(256) k_heads(const float* __restrict__ cls_w,
                                               const float* __restrict__ cls_b,
                                               const float* __restrict__ bbox_w,
                                               const float* __restrict__ bbox_b,
                                               float* __restrict__ out) {
    int idx = blockIdx.x * blockDim.x + threadIdx.x;
    if (idx >= BB * POST * 25) return;
    int row = idx / 25, col = idx - row * 25;
    float acc = (col < 5) ? cls_b[col] : bbox_b[col - 5];
    const float* x = &g_x7[(size_t)row * FC];
    if (col < 5) {
        for (int k = 0; k < FC; k++) acc += x[k] * __ldg(&cls_w[k * 5 + col]);
    } else {
        int c = col - 5;
        for (int k = 0; k < FC; k++) acc += x[k] * __ldg(&bbox_w[k * 20 + c]);
    }
    out[idx] = acc;
}

// ---------------- launch (inputs bound BY SIZE — order-proof) ----------------
extern "C" void kernel_launch(void* const* d_in, const int* in_sizes, int n_in,
                              void* d_out, int out_size) {
    const float *features = 0, *rpn_conv_w = 0, *rpn_conv_b = 0;
    const float *rpn_cls_w = 0, *rpn_cls_b = 0, *rpn_reg_w = 0, *rpn_reg_b = 0;
    const float *fc6_w = 0, *fc6_b = 0, *fc7_w = 0, *fc7_b = 0;
    const float *cls_w = 0, *cls_b = 0, *bbox_w = 0, *bbox_b = 0;

    for (int i = 0; i < n_in; i++) {
        const float* p = (const float*)d_in[i];
        switch (in_sizes[i]) {
            case 1536000:  features   = p; break;
            case 8294400:  rpn_conv_w = p; break;
            case 960:      rpn_conv_b = p; break;
            case 11520:    rpn_cls_w  = p; break;
            case 12:       rpn_cls_b  = p; break;
            case 46080:    rpn_reg_w  = p; break;
            case 48:       rpn_reg_b  = p; break;
            case 48168960: fc6_w      = p; break;
            case 1048576:  fc7_w      = p; break;
            case 5120:     cls_w      = p; break;
            case 5:        cls_b      = p; break;
            case 20480:    bbox_w     = p; break;
            case 20:       bbox_b     = p; break;
            case 1024:     if (!fc6_b) fc6_b = p; else fc7_b = p; break;
            default: break;
        }
    }
    float* out = (float*)d_out;

    // device symbols used as HOST-side kernel args must be resolved (ATS pitfall)
    float *p_x6 = 0, *p_x7 = 0;
    cudaGetSymbolAddress((void**)&p_x6, g_x6);
    cudaGetSymbolAddress((void**)&p_x7, g_x7);

    // --- conv: fp32 SIMT 128x128/8x8 (selection-critical, fp32-exact class) ---
    k_transpose_w<<<(9 * CC * CC + 255) / 256, 256>>>(rpn_conv_w);
    k_conv2<<<dim3((HWP + 127) / 128, (CC + 127) / 128, BB), 256>>>(features, rpn_conv_b);

    // --- rpn heads + proposal selection ---
    k_rpn<<<dim3((HWP + 127) / 128, 60, BB), 128>>>(rpn_cls_w, rpn_cls_b, rpn_reg_w, rpn_reg_b);
    k_key<<<(BB * NANCH + 255) / 256, 256>>>();
    k_rank<<<dim3((NANCH + 255) / 256, BB), 256>>>();
    k_decode<<<dim3((PRE + 255) / 256, BB), 256>>>();
    k_nms<<<BB, 1024>>>();
    k_roi<<<BB * POST, 256>>>(features);   // writes g_a6_hi/lo directly (fused split)

    // --- fc6 as bf16-split wmma GEMM ---
    k_split_fc6w<<<(FDIM * FC + 255) / 256, 256>>>(fc6_w);
    k_fc6_wmma<<<dim3(FC / 128, MPAD / 128, 1), 256>>>(fc6_b);

    // --- fc7 (fp32 SIMT) + heads ---
    k_gemm<<<dim3(FC / 64, (BB * POST + 63) / 64), 256>>>(p_x6, fc7_w, fc7_b, p_x7,
                                                          BB * POST, FC, FC, 1);
    k_heads<<<(BB * POST * 25 + 255) / 256, 256>>>(cls_w, cls_b, bbox_w, bbox_b, out);
}

// round 17
// speedup vs baseline: 1.2697x; 1.2697x over previous
#include <cuda_runtime.h>
#include <cuda_bf16.h>
#include <mma.h>
#include <math.h>
#include <stdint.h>

using namespace nvcuda;

// ---------------- problem constants ----------------
#define BB     2
#define CC     960
#define HH     20
#define WW     40
#define HWP    800        // H*W
#define AA     12
#define NANCH  9600       // HWP*AA
#define PRE    1000
#define POST   500
#define POOLN  7
#define FDIM   47040      // CC*49
#define FC     1024
#define BBOX_CLIP 4.135166556742356f
#define NMS_TH 0.7f

#define MPAD   1024       // padded M for fc6 GEMM

// ---------------- scratch (static device globals; no allocations) ----------------
__device__ float              g_wT[9 * CC * CC];    // conv weights transposed [tap][ci][co]
__device__ float              g_t[BB * CC * HWP];   // conv output (relu)
__device__ float              g_obj[BB * NANCH];
__device__ float              g_dlt[BB * NANCH * 4];
__device__ unsigned long long g_keys[BB * NANCH];
__device__ int                g_topidx[BB * PRE];
__device__ float              g_boxes[BB * PRE * 4];
__device__ int                g_keep[BB * POST];
__device__ float              g_x6[BB * POST * FC];
__device__ float              g_x7[BB * POST * FC];

// fc6 bf16 split buffers. g_a6_* rows 1000..1023 are never written -> stay zero (BSS).
__device__ __align__(128) __nv_bfloat16 g_a6_hi[MPAD * FDIM];    // fc6 A = pooled [M x K]
__device__ __align__(128) __nv_bfloat16 g_a6_lo[MPAD * FDIM];
__device__ __align__(128) __nv_bfloat16 g_b6_hi[FDIM * FC];      // fc6 B = fc6_w  [K x N]
__device__ __align__(128) __nv_bfloat16 g_b6_lo[FDIM * FC];

// ---------------- split helper ----------------
__device__ __forceinline__ void split_bf16(float v, __nv_bfloat16& hi, __nv_bfloat16& lo) {
    hi = __float2bfloat16(v);
    lo = __float2bfloat16(v - __bfloat162float(hi));
}

// ---------------- 1. weight transpose ----------------
__global__ void __launch_bounds__(256) k_transpose_w(const float* __restrict__ w) {
    int d = blockIdx.x * blockDim.x + threadIdx.x;
    if (d >= 9 * CC * CC) return;
    int tap = d / (CC * CC);
    int rem = d - tap * (CC * CC);
    int ci = rem / CC;
    int co = rem - ci * CC;
    int ky = tap / 3, kx = tap - ky * 3;
    g_wT[d] = w[((co * CC + ci) * 3 + ky) * 3 + kx];
}

// ---------------- 2. 3x3 conv + bias + relu (R8/R15 proven fp32 SIMT) -----------
__global__ void __launch_bounds__(256) k_conv(const float* __restrict__ x,
                                              const float* __restrict__ bias) {
    __shared__ float Ws[16][64];
    __shared__ float Xs[16][64];
    const int b  = blockIdx.z;
    const int co0 = blockIdx.y * 64;
    const int p0  = blockIdx.x * 64;
    const int tid = threadIdx.x;
    const int ti = tid >> 4, tj = tid & 15;

    float acc[4][4];
#pragma unroll
    for (int i = 0; i < 4; i++)
#pragma unroll
        for (int j = 0; j < 4; j++) acc[i][j] = 0.f;

    for (int tap = 0; tap < 9; ++tap) {
        const int dy = tap / 3 - 1, dx = tap % 3 - 1;
        for (int ci0 = 0; ci0 < CC; ci0 += 16) {
#pragma unroll
            for (int i = 0; i < 4; i++) {
                int e = tid + i * 256;
                int k = e >> 6, m = e & 63;
                Ws[k][m] = g_wT[(tap * CC + ci0 + k) * CC + co0 + m];
            }
#pragma unroll
            for (int i = 0; i < 4; i++) {
                int e = tid + i * 256;
                int k = e >> 6, j = e & 63;
                int p = p0 + j;
                float v = 0.f;
                if (p < HWP) {
                    int y = p / WW, xx = p - y * WW;
                    int yy = y + dy, xs = xx + dx;
                    if (yy >= 0 && yy < HH && xs >= 0 && xs < WW)
                        v = x[((b * CC + ci0 + k) * HH + yy) * WW + xs];
                }
                Xs[k][j] = v;
            }
            __syncthreads();
#pragma unroll
            for (int k = 0; k < 16; k++) {
                float a0 = Ws[k][ti * 4 + 0], a1 = Ws[k][ti * 4 + 1],
                      a2 = Ws[k][ti * 4 + 2], a3 = Ws[k][ti * 4 + 3];
                float b0 = Xs[k][tj * 4 + 0], b1 = Xs[k][tj * 4 + 1],
                      b2 = Xs[k][tj * 4 + 2], b3 = Xs[k][tj * 4 + 3];
                acc[0][0] += a0 * b0; acc[0][1] += a0 * b1; acc[0][2] += a0 * b2; acc[0][3] += a0 * b3;
                acc[1][0] += a1 * b0; acc[1][1] += a1 * b1; acc[1][2] += a1 * b2; acc[1][3] += a1 * b3;
                acc[2][0] += a2 * b0; acc[2][1] += a2 * b1; acc[2][2] += a2 * b2; acc[2][3] += a2 * b3;
                acc[3][0] += a3 * b0; acc[3][1] += a3 * b1; acc[3][2] += a3 * b2; acc[3][3] += a3 * b3;
            }
            __syncthreads();
        }
    }
#pragma unroll
    for (int ii = 0; ii < 4; ii++) {
        int co = co0 + ti * 4 + ii;
        float bs = bias[co];
#pragma unroll
        for (int jj = 0; jj < 4; jj++) {
            int p = p0 + tj * 4 + jj;
            if (p < HWP) {
                float v = acc[ii][jj] + bs;
                g_t[(b * CC + co) * HWP + p] = v > 0.f ? v : 0.f;
            }
        }
    }
}

// ---------------- fc6 weight split ----------------
__global__ void __launch_bounds__(256) k_split_fc6w(const float* __restrict__ w) {
    int i = blockIdx.x * 256 + threadIdx.x;
    if (i >= FDIM * FC) return;
    __nv_bfloat16 hi, lo; split_bf16(w[i], hi, lo);
    g_b6_hi[i] = hi; g_b6_lo[i] = lo;
}

// ---------------- fc6: bf16-split wmma GEMM (64x128 tile, 128 CTAs) -------------
// Retiled from 128x128 (64 CTAs, 43% SM coverage) to 64x128 (128 CTAs, 86%).
// Warp grid 2x4 of 32x32 tiles; K-order unchanged -> bit-identical results.
#define LDA 40    // 32 + 8 bf16: 80B row stride
#define LDB 136   // 128 + 8 bf16: 272B row stride
#define LDS 16    // epilogue scratch ld: 64B (wmma-legal)

__global__ void __launch_bounds__(256) k_fc6_wmma(const float* __restrict__ bias) {
    __shared__ __align__(16) __nv_bfloat16 AsH[64 * LDA], AsL[64 * LDA];
    __shared__ __align__(16) __nv_bfloat16 BsH[32 * LDB], BsL[32 * LDB];
    __shared__ __align__(16) float scr[8][16 * LDS];

    const int tid = threadIdx.x, wid = tid >> 5, lane = tid & 31;
    const int m0 = blockIdx.y * 64, n0 = blockIdx.x * 128;
    const int wm = wid >> 2, wn = wid & 3;   // 2 x 4 warp grid, 32x32 each

    wmma::fragment<wmma::accumulator, 16, 16, 16, float> acc[2][2];
#pragma unroll
    for (int i = 0; i < 2; i++)
#pragma unroll
        for (int j = 0; j < 2; j++) wmma::fill_fragment(acc[i][j], 0.f);

    for (int k0 = 0; k0 < FDIM; k0 += 32) {
        // A: 64 rows x 32 k = 256 uint4 per matrix (1 per thread)
        {
            int r = tid >> 2, q = tid & 3;
            size_t go = (size_t)(m0 + r) * FDIM + k0 + q * 8;
            *(uint4*)&AsH[r * LDA + q * 8] = *(const uint4*)&g_a6_hi[go];
            *(uint4*)&AsL[r * LDA + q * 8] = *(const uint4*)&g_a6_lo[go];
        }
        // B: 32 k rows x 128 = 512 uint4 per matrix (2 per thread)
#pragma unroll
        for (int e = tid; e < 512; e += 256) {
            int r = e >> 4, q = e & 15;
            size_t go = (size_t)(k0 + r) * FC + n0 + q * 8;
            *(uint4*)&BsH[r * LDB + q * 8] = *(const uint4*)&g_b6_hi[go];
            *(uint4*)&BsL[r * LDB + q * 8] = *(const uint4*)&g_b6_lo[go];
        }
        __syncthreads();

#pragma unroll
        for (int kk = 0; kk < 2; kk++) {
            wmma::fragment<wmma::matrix_a, 16, 16, 16, __nv_bfloat16, wmma::row_major> ah[2], al[2];
            wmma::fragment<wmma::matrix_b, 16, 16, 16, __nv_bfloat16, wmma::row_major> bh[2], bl[2];
#pragma unroll
            for (int i = 0; i < 2; i++) {
                wmma::load_matrix_sync(ah[i], &AsH[(wm * 32 + i * 16) * LDA + kk * 16], LDA);
                wmma::load_matrix_sync(al[i], &AsL[(wm * 32 + i * 16) * LDA + kk * 16], LDA);
            }
#pragma unroll
            for (int j = 0; j < 2; j++) {
                wmma::load_matrix_sync(bh[j], &BsH[(kk * 16) * LDB + wn * 32 + j * 16], LDB);
                wmma::load_matrix_sync(bl[j], &BsL[(kk * 16) * LDB + wn * 32 + j * 16], LDB);
            }
#pragma unroll
            for (int i = 0; i < 2; i++)
#pragma unroll
                for (int j = 0; j < 2; j++) {
                    wmma::mma_sync(acc[i][j], ah[i], bh[j], acc[i][j]);
                    wmma::mma_sync(acc[i][j], ah[i], bl[j], acc[i][j]);
                    wmma::mma_sync(acc[i][j], al[i], bh[j], acc[i][j]);
                }
        }
        __syncthreads();
    }

#pragma unroll
    for (int i = 0; i < 2; i++)
#pragma unroll
        for (int j = 0; j < 2; j++) {
            wmma::store_matrix_sync(&scr[wid][0], acc[i][j], LDS, wmma::mem_row_major);
            __syncwarp();
#pragma unroll
            for (int e = lane; e < 256; e += 32) {
                int r = e >> 4, c = e & 15;
                int gm = m0 + wm * 32 + i * 16 + r;
                int gn = n0 + wn * 32 + j * 16 + c;
                if (gm < BB * POST) {
                    float v = scr[wid][r * LDS + c] + bias[gn];
                    g_x6[(size_t)gm * FC + gn] = v > 0.f ? v : 0.f;
                }
            }
            __syncwarp();
        }
}

// ---------------- rpn cls/reg heads ----------------
__global__ void __launch_bounds__(128) k_rpn(const float* __restrict__ cls_w,
                                             const float* __restrict__ cls_b,
                                             const float* __restrict__ reg_w,
                                             const float* __restrict__ reg_b) {
    const int p = blockIdx.x * blockDim.x + threadIdx.x;
    if (p >= HWP) return;
    const int r = blockIdx.y;   // 0..59
    const int b = blockIdx.z;
    const float* wrow = (r < AA) ? (cls_w + r * CC) : (reg_w + (r - AA) * CC);
    float acc = (r < AA) ? cls_b[r] : reg_b[r - AA];
    const float* tp = g_t + (size_t)b * CC * HWP + p;
    for (int k = 0; k < CC; k++)
        acc += tp[k * HWP] * __ldg(&wrow[k]);
    if (r < AA) {
        g_obj[b * NANCH + p * AA + r] = acc;
    } else {
        int a48 = r - AA;
        int a = a48 >> 2, c = a48 & 3;
        g_dlt[((size_t)b * NANCH + p * AA + a) * 4 + c] = acc;
    }
}

// ---------------- top-1000 via exact rank selection ----------------
__device__ __forceinline__ unsigned int mapf(float f) {
    unsigned int u = __float_as_uint(f);
    return (u & 0x80000000u) ? ~u : (u | 0x80000000u);
}
__global__ void __launch_bounds__(256) k_key() {
    int i = blockIdx.x * blockDim.x + threadIdx.x;
    if (i >= BB * NANCH) return;
    int b = i / NANCH;
    int j = i - b * NANCH;
    unsigned int u = mapf(g_obj[i]);
    g_keys[i] = ((unsigned long long)(~u) << 32) | (unsigned int)j;
}
__global__ void __launch_bounds__(256) k_rank() {
    const int b = blockIdx.y;
    const int i = blockIdx.x * blockDim.x + threadIdx.x;
    if (i >= NANCH) return;
    const unsigned long long* keys = g_keys + (size_t)b * NANCH;
    const unsigned long long ki = keys[i];
    int cnt = 0;
    for (int j = 0; j < NANCH; j++)
        cnt += (keys[j] < ki);
    if (cnt < PRE)
        g_topidx[b * PRE + cnt] = i;
}

// ---------------- decode + clip ----------------
__global__ void __launch_bounds__(256) k_decode() {
    const int b = blockIdx.y;
    const int i = blockIdx.x * blockDim.x + threadIdx.x;
    if (i >= PRE) return;
    int idx = g_topidx[b * PRE + i];
    int p = idx / AA, a = idx - p * AA;
    int y = p / WW, xx = p - y * WW;
    int r = a >> 2, s = a & 3;
    const float sizes[4] = {32.f, 64.f, 128.f, 256.f};
    const float ratios[3] = {0.5f, 1.f, 2.f};
    float hr = sqrtf(ratios[r]);
    float wr = 1.0f / hr;
    float wa = wr * sizes[s];
    float ha = hr * sizes[s];
    float cxa = xx * 16.0f, cya = y * 16.0f;
    const float* d = &g_dlt[((size_t)b * NANCH + idx) * 4];
    float dx = d[0], dy = d[1];
    float dw = fminf(d[2], BBOX_CLIP), dh = fminf(d[3], BBOX_CLIP);
    float cx = dx * wa + cxa, cy = dy * ha + cya;
    float w = expf(dw) * wa, h = expf(dh) * ha;
    float x1 = cx - 0.5f * w, y1 = cy - 0.5f * h;
    float x2 = cx + 0.5f * w, y2 = cy + 0.5f * h;
    x1 = fminf(fmaxf(x1, 0.f), 640.f);
    y1 = fminf(fmaxf(y1, 0.f), 320.f);
    x2 = fminf(fmaxf(x2, 0.f), 640.f);
    y2 = fminf(fmaxf(y2, 0.f), 320.f);
    float* bx = &g_boxes[((size_t)b * PRE + i) * 4];
    bx[0] = x1; bx[1] = y1; bx[2] = x2; bx[3] = y2;
}

// ---------------- NMS ----------------
__global__ void __launch_bounds__(1024) k_nms() {
    __shared__ float bx1[PRE], by1[PRE], bx2[PRE], by2[PRE], barea[PRE];
    __shared__ int msk[PRE];
    const int b = blockIdx.x, j = threadIdx.x;
    if (j < PRE) {
        const float* bx = &g_boxes[((size_t)b * PRE + j) * 4];
        bx1[j] = bx[0]; by1[j] = bx[1]; bx2[j] = bx[2]; by2[j] = bx[3];
        barea[j] = (bx[2] - bx[0]) * (bx[3] - bx[1]);
        msk[j] = 1;
    }
    __syncthreads();
    for (int i = 0; i < PRE - 1; i++) {
        bool mi = (msk[i] != 0);
        if (mi && j < PRE && j > i && msk[j]) {
            float lx = fmaxf(bx1[i], bx1[j]);
            float ly = fmaxf(by1[i], by1[j]);
            float rx = fminf(bx2[i], bx2[j]);
            float ry = fminf(by2[i], by2[j]);
            float w = fmaxf(rx - lx, 0.f), h = fmaxf(ry - ly, 0.f);
            float inter = w * h;
            float iou = inter / (barea[i] + barea[j] - inter + 1e-6f);
            if (iou > NMS_TH) msk[j] = 0;
        }
        __syncthreads();
    }
    if (j == 0) {
        int k = 0;
        for (int i = 0; i < PRE && k < POST; i++)
            if (msk[i]) g_keep[b * POST + k++] = i;
        for (int i = 0; i < PRE && k < POST; i++)
            if (!msk[i]) g_keep[b * POST + k++] = i;
    }
}

// ---------------- ROI align (warp-per-channel, coalesced, fused bf16 split) -----
struct Geo { int i00, i01, i10, i11; float w00, w01, w10, w11; };
__global__ void __launch_bounds__(256) k_roi(const float* __restrict__ feat) {
    __shared__ float rows[8][HWP];
    __shared__ Geo geo[49 * 4];
    __shared__ float box[4];
    const int ng = blockIdx.x;
    const int b = ng / POST;
    const int nl = ng - b * POST;
    const int tid = threadIdx.x;
    const int wid = tid >> 5, lane = tid & 31;

    if (tid == 0) {
        int kidx = g_keep[b * POST + nl];
        const float* bx = &g_boxes[((size_t)b * PRE + kidx) * 4];
        box[0] = bx[0]; box[1] = bx[1]; box[2] = bx[2]; box[3] = bx[3];
    }
    __syncthreads();
    if (tid < 49 * 4) {
        int bin = tid >> 2, s = tid & 3;
        int py = bin / POOLN, px = bin - py * POOLN;
        int sy = s >> 1, sx = s & 1;
        float x1 = box[0] / 16.0f, y1 = box[1] / 16.0f;
        float x2 = box[2] / 16.0f, y2 = box[3] / 16.0f;
        float rw = fmaxf(x2 - x1, 1.0f), rh = fmaxf(y2 - y1, 1.0f);
        float bw = rw / POOLN, bh = rh / POOLN;
        float suby = (sy == 0) ? 0.25f : 0.75f;
        float subx = (sx == 0) ? 0.25f : 0.75f;
        float ys = y1 + (py + suby) * bh;
        float xs = x1 + (px + subx) * bw;
        ys = fminf(fmaxf(ys, 0.f), (float)(HH - 1));
        xs = fminf(fmaxf(xs, 0.f), (float)(WW - 1));
        int y0 = (int)floorf(ys), x0 = (int)floorf(xs);
        int y1i = min(y0 + 1, HH - 1), x1i = min(x0 + 1, WW - 1);
        float wy = ys - (float)y0, wx = xs - (float)x0;
        Geo g;
        g.i00 = y0 * WW + x0;  g.i01 = y0 * WW + x1i;
        g.i10 = y1i * WW + x0; g.i11 = y1i * WW + x1i;
        g.w00 = (1.f - wy) * (1.f - wx) * 0.25f;
        g.w01 = (1.f - wy) * wx * 0.25f;
        g.w10 = wy * (1.f - wx) * 0.25f;
        g.w11 = wy * wx * 0.25f;
        geo[tid] = g;
    }
    __syncthreads();

    for (int c = wid; c < CC; c += 8) {
        const float* f = feat + ((size_t)b * CC + c) * HWP;
#pragma unroll
        for (int i = lane; i < HWP; i += 32)
            rows[wid][i] = f[i];
        __syncwarp();
        size_t dbase = (size_t)ng * FDIM + (size_t)c * 49;
        for (int bin = lane; bin < 49; bin += 32) {
            float acc = 0.f;
#pragma unroll
            for (int s = 0; s < 4; s++) {
                Geo g = geo[bin * 4 + s];
                acc += g.w00 * rows[wid][g.i00] + g.w01 * rows[wid][g.i01] +
                       g.w10 * rows[wid][g.i10] + g.w11 * rows[wid][g.i11];
            }
            __nv_bfloat16 hi, lo; split_bf16(acc, hi, lo);
            g_a6_hi[dbase + bin] = hi;
            g_a6_lo[dbase + bin] = lo;
        }
        __syncwarp();
    }
}

// ---------------- fp32 tiled GEMM (fc7) ----------------
__global__ void __launch_bounds__(256) k_gemm(const float* __restrict__ A,
                                              const float* __restrict__ Bm,
                                              const float* __restrict__ bias,
                                              float* __restrict__ Cc,
                                              int M, int N, int K, int dorelu) {
    __shared__ float As[16][64];
    __shared__ float Bs[16][64];
    const int n0 = blockIdx.x * 64;
    const int m0 = blockIdx.y * 64;
    const int tid = threadIdx.x;
    const int ti = tid >> 4, tj = tid & 15;
    float acc[4][4];
#pragma unroll
    for (int i = 0; i < 4; i++)
#pragma unroll
        for (int j = 0; j < 4; j++) acc[i][j] = 0.f;

    for (int k0 = 0; k0 < K; k0 += 16) {
#pragma unroll
        for (int i = 0; i < 4; i++) {
            int e = tid + i * 256;
            int m = e >> 4, k = e & 15;
            int row = m0 + m;
            As[k][m] = (row < M) ? A[(size_t)row * K + k0 + k] : 0.f;
        }
#pragma unroll
        for (int i = 0; i < 4; i++) {
            int e = tid + i * 256;
            int k = e >> 6, n = e & 63;
            Bs[k][n] = Bm[(size_t)(k0 + k) * N + n0 + n];
        }
        __syncthreads();
#pragma unroll
        for (int k = 0; k < 16; k++) {
            float4 av = *(const float4*)&As[k][ti * 4];
            float4 bv = *(const float4*)&Bs[k][tj * 4];
            acc[0][0] += av.x * bv.x; acc[0][1] += av.x * bv.y; acc[0][2] += av.x * bv.z; acc[0][3] += av.x * bv.w;
            acc[1][0] += av.y * bv.x; acc[1][1] += av.y * bv.y; acc[1][2] += av.y * bv.z; acc[1][3] += av.y * bv.w;
            acc[2][0] += av.z * bv.x; acc[2][1] += av.z * bv.y; acc[2][2] += av.z * bv.z; acc[2][3] += av.z * bv.w;
            acc[3][0] += av.w * bv.x; acc[3][1] += av.w * bv.y; acc[3][2] += av.w * bv.z; acc[3][3] += av.w * bv.w;
        }
        __syncthreads();
    }
#pragma unroll
    for (int ii = 0; ii < 4; ii++) {
        int row = m0 + ti * 4 + ii;
        if (row < M) {
#pragma unroll
            for (int jj = 0; jj < 4; jj++) {
                int col = n0 + tj * 4 + jj;
                float v = acc[ii][jj] + bias[col];
                if (dorelu) v = v > 0.f ? v : 0.f;
                Cc[(size_t)row * N + col] = v;
            }
        }
    }
}

// ---------------- final heads ----------------
__global__ void __launch_bounds__(256) k_heads(const float* __restrict__ cls_w,
                                               const float* __restrict__ cls_b,
                                               const float* __restrict__ bbox_w,
                                               const float* __restrict__ bbox_b,
                                               float* __restrict__ out) {
    int idx = blockIdx.x * blockDim.x + threadIdx.x;
    if (idx >= BB * POST * 25) return;
    int row = idx / 25, col = idx - row * 25;
    float acc = (col < 5) ? cls_b[col] : bbox_b[col - 5];
    const float* x = &g_x7[(size_t)row * FC];
    if (col < 5) {
        for (int k = 0; k < FC; k++) acc += x[k] * __ldg(&cls_w[k * 5 + col]);
    } else {
        int c = col - 5;
        for (int k = 0; k < FC; k++) acc += x[k] * __ldg(&bbox_w[k * 20 + c]);
    }
    out[idx] = acc;
}

// ---------------- launch (inputs bound BY SIZE — order-proof) ----------------
extern "C" void kernel_launch(void* const* d_in, const int* in_sizes, int n_in,
                              void* d_out, int out_size) {
    const float *features = 0, *rpn_conv_w = 0, *rpn_conv_b = 0;
    const float *rpn_cls_w = 0, *rpn_cls_b = 0, *rpn_reg_w = 0, *rpn_reg_b = 0;
    const float *fc6_w = 0, *fc6_b = 0, *fc7_w = 0, *fc7_b = 0;
    const float *cls_w = 0, *cls_b = 0, *bbox_w = 0, *bbox_b = 0;

    for (int i = 0; i < n_in; i++) {
        const float* p = (const float*)d_in[i];
        switch (in_sizes[i]) {
            case 1536000:  features   = p; break;
            case 8294400:  rpn_conv_w = p; break;
            case 960:      rpn_conv_b = p; break;
            case 11520:    rpn_cls_w  = p; break;
            case 12:       rpn_cls_b  = p; break;
            case 46080:    rpn_reg_w  = p; break;
            case 48:       rpn_reg_b  = p; break;
            case 48168960: fc6_w      = p; break;
            case 1048576:  fc7_w      = p; break;
            case 5120:     cls_w      = p; break;
            case 5:        cls_b      = p; break;
            case 20480:    bbox_w     = p; break;
            case 20:       bbox_b     = p; break;
            case 1024:     if (!fc6_b) fc6_b = p; else fc7_b = p; break;
            default: break;
        }
    }
    float* out = (float*)d_out;

    // device symbols used as HOST-side kernel args must be resolved (ATS pitfall)
    float *p_x6 = 0, *p_x7 = 0;
    cudaGetSymbolAddress((void**)&p_x6, g_x6);
    cudaGetSymbolAddress((void**)&p_x7, g_x7);

    // --- conv: R8/R15 proven fp32 SIMT (selection-critical) ---
    k_transpose_w<<<(9 * CC * CC + 255) / 256, 256>>>(rpn_conv_w);
    k_conv<<<dim3((HWP + 63) / 64, CC / 64, BB), 256>>>(features, rpn_conv_b);

    // --- rpn heads + proposal selection ---
    k_rpn<<<dim3((HWP + 127) / 128, 60, BB), 128>>>(rpn_cls_w, rpn_cls_b, rpn_reg_w, rpn_reg_b);
    k_key<<<(BB * NANCH + 255) / 256, 256>>>();
    k_rank<<<dim3((NANCH + 255) / 256, BB), 256>>>();
    k_decode<<<dim3((PRE + 255) / 256, BB), 256>>>();
    k_nms<<<BB, 1024>>>();
    k_roi<<<BB * POST, 256>>>(features);   // writes g_a6_hi/lo directly (fused split)

    // --- fc6 as bf16-split wmma GEMM (64x128 tiles -> 128 CTAs) ---
    k_split_fc6w<<<(FDIM * FC + 255) / 256, 256>>>(fc6_w);
    k_fc6_wmma<<<dim3(FC / 128, MPAD / 64, 1), 256>>>(fc6_b);

    // --- fc7 (fp32 SIMT) + heads ---
    k_gemm<<<dim3(FC / 64, (BB * POST + 63) / 64), 256>>>(p_x6, fc7_w, fc7_b, p_x7,
                                                          BB * POST, FC, FC, 1);
    k_heads<<<(BB * POST * 25 + 255) / 256, 256>>>(cls_w, cls_b, bbox_w, bbox_b, out);
}